// round 7
// baseline (speedup 1.0000x reference)
#include <cuda_runtime.h>
#include <cuda_fp16.h>
#include <cstdint>

#define N_NODES 8192
#define IN_DIM  256
#define OUT_DIM 128
#define NCOLS   144     // 128 out cols + g col (idx 128) + 15 pad
#define CH_K    64      // K per chunk (fp16), 128B rows
#define SPLITS  4

// ---------------- device scratch (zero-initialized at module load) ---------
__device__ __align__(16) __half Pt_f16[NCOLS * N_NODES];      // [n][k], rows>128 stay 0
__device__ __align__(16) float  Wh_buf[N_NODES * OUT_DIM];
__device__ __align__(16) float  e_buf[N_NODES];
__device__ unsigned emax_enc;
__device__ __align__(16) float part_buf[SPLITS * N_NODES * NCOLS];

// ---------------- helpers ---------------------------------------------------
__device__ __forceinline__ uint32_t smem_u32(const void* p) {
    uint32_t a;
    asm("{ .reg .u64 t; cvta.to.shared.u64 t, %1; cvt.u32.u64 %0, t; }"
        : "=r"(a) : "l"(p));
    return a;
}
__device__ __forceinline__ unsigned fenc(float f) {
    unsigned u = __float_as_uint(f);
    return u ^ ((unsigned)((int)u >> 31) | 0x80000000u);
}
__device__ __forceinline__ float fdec(unsigned v) {
    unsigned u = (v & 0x80000000u) ? (v ^ 0x80000000u) : ~v;
    return __uint_as_float(u);
}
// SW128 swizzle for [rows][64 halves] tiles (128B rows, 16B chunks 0..7)
__device__ __forceinline__ uint32_t swz128(int row, int chunk) {
    return (uint32_t)(row * 128 + ((chunk ^ (row & 7)) << 4));
}

#define LDSM_X4(r, addr) \
    asm volatile("ldmatrix.sync.aligned.m8n8.x4.shared.b16 {%0,%1,%2,%3}, [%4];" \
        : "=r"((r)[0]), "=r"((r)[1]), "=r"((r)[2]), "=r"((r)[3]) : "r"(addr))
#define LDSM_X2(r0, r1, addr) \
    asm volatile("ldmatrix.sync.aligned.m8n8.x2.shared.b16 {%0,%1}, [%2];" \
        : "=r"(r0), "=r"(r1) : "r"(addr))
#define MMA16816(c, a, b0, b1) \
    asm volatile("mma.sync.aligned.m16n8k16.row.col.f32.f16.f16.f32 " \
        "{%0,%1,%2,%3},{%4,%5,%6,%7},{%8,%9},{%0,%1,%2,%3};" \
        : "+f"((c)[0]), "+f"((c)[1]), "+f"((c)[2]), "+f"((c)[3]) \
        : "r"((a)[0]), "r"((a)[1]), "r"((a)[2]), "r"((a)[3]), "r"(b0), "r"(b1))
#define CP_ASYNC16(daddr, gptr) \
    asm volatile("cp.async.cg.shared.global [%0], [%1], 16;" \
        :: "r"(daddr), "l"(gptr) : "memory")
#define CP_COMMIT() asm volatile("cp.async.commit_group;" ::: "memory")
#define CP_WAIT0()  asm volatile("cp.async.wait_group 0;" ::: "memory")

// ---------------------------------------------------------------------------
// Phase 1: Wh = X @ W^T -> Wh_buf (fp32), e = relu(Wh)@a_w -> e_buf, atomicMax.
// 512 blocks x 16 nodes, 256 threads, double-buffered smem + reg prefetch.
// ---------------------------------------------------------------------------
__global__ __launch_bounds__(256)
void gat_phase1(const float* __restrict__ X,
                const float* __restrict__ W,
                const float* __restrict__ a_w)
{
    __shared__ float Xs[2][32 * 20];
    __shared__ float Ws[2][32 * 132];
    __shared__ float aw_s[OUT_DIM];

    const int t  = threadIdx.x;
    const int tx = t & 15;
    const int ty = t >> 4;
    const int node0 = blockIdx.x * 16;

    if (t < OUT_DIM) aw_s[t] = a_w[t];

    float acc[8];
    #pragma unroll
    for (int j = 0; j < 8; j++) acc[j] = 0.0f;

    // prefetch registers
    float4 xv;
    float4 wv[4];
    const int xr = t >> 3, xq = t & 7;      // X loaders: threads 0..127
    const int wq = t & 7,  wcb = t >> 3;

    auto LDGX = [&](int k0) {
        if (t < 128)
            xv = *reinterpret_cast<const float4*>(
                &X[(node0 + xr) * IN_DIM + k0 + 4 * xq]);
    };
    auto LDGW = [&](int k0) {
        #pragma unroll
        for (int it = 0; it < 4; it++) {
            const int c = wcb + 32 * it;
            wv[it] = *reinterpret_cast<const float4*>(&W[c * IN_DIM + k0 + 4 * wq]);
        }
    };
    auto STSX = [&](int b) {
        if (t < 128) {
            Xs[b][(4*xq+0)*20 + xr] = xv.x; Xs[b][(4*xq+1)*20 + xr] = xv.y;
            Xs[b][(4*xq+2)*20 + xr] = xv.z; Xs[b][(4*xq+3)*20 + xr] = xv.w;
        }
    };
    auto STSW = [&](int b) {
        #pragma unroll
        for (int it = 0; it < 4; it++) {
            const int c = wcb + 32 * it;
            Ws[b][(4*wq+0)*132 + c] = wv[it].x;
            Ws[b][(4*wq+1)*132 + c] = wv[it].y;
            Ws[b][(4*wq+2)*132 + c] = wv[it].z;
            Ws[b][(4*wq+3)*132 + c] = wv[it].w;
        }
    };

    LDGX(0); LDGW(0); STSX(0); STSW(0);
    __syncthreads();

    for (int i = 0; i < 8; i++) {
        const int b = i & 1;
        if (i < 7) { LDGX(32 * (i + 1)); LDGW(32 * (i + 1)); }

        #pragma unroll
        for (int k = 0; k < 32; k++) {
            float a = Xs[b][k * 20 + ty];
            float4 b0 = *reinterpret_cast<const float4*>(&Ws[b][k * 132 + 8 * tx]);
            float4 b1 = *reinterpret_cast<const float4*>(&Ws[b][k * 132 + 8 * tx + 4]);
            acc[0] = fmaf(a, b0.x, acc[0]); acc[1] = fmaf(a, b0.y, acc[1]);
            acc[2] = fmaf(a, b0.z, acc[2]); acc[3] = fmaf(a, b0.w, acc[3]);
            acc[4] = fmaf(a, b1.x, acc[4]); acc[5] = fmaf(a, b1.y, acc[5]);
            acc[6] = fmaf(a, b1.z, acc[6]); acc[7] = fmaf(a, b1.w, acc[7]);
        }
        if (i < 7) { STSX(b ^ 1); STSW(b ^ 1); }
        __syncthreads();
    }

    // e = relu(Wh) @ a_w, reduced over the 16 tx lanes
    float ep = 0.0f;
    #pragma unroll
    for (int j = 0; j < 8; j++)
        ep = fmaf(fmaxf(acc[j], 0.0f), aw_s[8 * tx + j], ep);
    #pragma unroll
    for (int m = 8; m >= 1; m >>= 1)
        ep += __shfl_xor_sync(0xffffffffu, ep, m, 16);

    const int row = node0 + ty;
    *reinterpret_cast<float4*>(&Wh_buf[row * OUT_DIM + 8 * tx]) =
        make_float4(acc[0], acc[1], acc[2], acc[3]);
    *reinterpret_cast<float4*>(&Wh_buf[row * OUT_DIM + 8 * tx + 4]) =
        make_float4(acc[4], acc[5], acc[6], acc[7]);
    if (tx == 0) {
        e_buf[row] = ep;
        atomicMax(&emax_enc, fenc(ep));
    }
}

// ---------------------------------------------------------------------------
// Scale/transpose: Pt_f16[c][node] = fp16(g[node] * Wh[node][c]), row128 = g.
// 32x32 smem transpose tiles; grid = 256 node-tiles x 4 col-tiles.
// ---------------------------------------------------------------------------
__global__ __launch_bounds__(256)
void gat_scale()
{
    __shared__ float S[32 * 33];
    __shared__ float gs[32];

    const int t = threadIdx.x;
    const int node0 = (blockIdx.x >> 2) * 32;
    const int c0 = (blockIdx.x & 3) * 32;

    {   // coalesced tile load: 32 nodes x 32 cols
        const int r = t >> 3, cq = t & 7;
        float4 v = *reinterpret_cast<const float4*>(
            &Wh_buf[(node0 + r) * OUT_DIM + c0 + 4 * cq]);
        S[r * 33 + 4*cq + 0] = v.x; S[r * 33 + 4*cq + 1] = v.y;
        S[r * 33 + 4*cq + 2] = v.z; S[r * 33 + 4*cq + 3] = v.w;
    }
    if (t < 32) gs[t] = expf(e_buf[node0 + t] - fdec(emax_enc));
    __syncthreads();

    {   // transposed write: each thread 1 col x 4 nodes (8B)
        const int oc = t >> 3, nq = t & 7;
        __half h[4];
        #pragma unroll
        for (int j = 0; j < 4; j++) {
            const int n = nq * 4 + j;
            h[j] = __float2half_rn(gs[n] * S[n * 33 + oc]);
        }
        *reinterpret_cast<uint2*>(
            &Pt_f16[(size_t)(c0 + oc) * N_NODES + node0 + nq * 4]) =
            *reinterpret_cast<uint2*>(h);
    }
    if (c0 == 0 && t < 32)
        Pt_f16[(size_t)128 * N_NODES + node0 + t] = __float2half_rn(gs[t]);
}

// ---------------------------------------------------------------------------
// Phase 2: fp16 HMMA GEMM. part[split] = A_f16[128 x 2048] @ Pt^T
// CTA: M=128, N=144, K-chunk 64; 256 threads = 8 warps (4m x 2n, m32 x n72).
// 2-stage pipeline, 32 iterations (one barrier each). 2 CTAs/SM.
// ---------------------------------------------------------------------------
#define STG_BYTES 34816     // A 16384 + B 18432
#define B_OFF     16384
#define PH2_SMEM  (2 * STG_BYTES)

__global__ __launch_bounds__(256, 2)
void gat_phase2(const float* __restrict__ A)
{
    extern __shared__ unsigned char sm[];
    const uint32_t sbase0 = smem_u32(sm);

    const int t     = threadIdx.x;
    const int lane  = t & 31;
    const int wid   = t >> 5;
    const int tile  = blockIdx.x & 63;
    const int split = blockIdx.x >> 6;
    const int r0    = tile * 128;
    const int kbase = split * (N_NODES / SPLITS);
    const int NCH   = (N_NODES / SPLITS) / CH_K;   // 32

    const int m0 = (wid & 3) * 32;
    const int n0 = (wid >> 2) * 72;

    float C0[9][4], C1[9][4];
    #pragma unroll
    for (int j = 0; j < 9; j++)
        #pragma unroll
        for (int q = 0; q < 4; q++) { C0[j][q] = 0.0f; C1[j][q] = 0.0f; }

    float4 av[4];                      // 16 floats = half of this thread's 32
    const int ar = t >> 1;             // row 0..127
    const int ac = t & 1;              // 32-float half of the 64-K row

    auto LDG_A = [&](int i, int p) {
        const float4* src = reinterpret_cast<const float4*>(
            &A[(size_t)(r0 + ar) * N_NODES + kbase + i * CH_K + ac * 32 + p * 16]);
        av[0] = src[0]; av[1] = src[1]; av[2] = src[2]; av[3] = src[3];
    };
    auto STS_A = [&](int stg, int p) {
        const int bc = ac * 4 + p * 2;
        #pragma unroll
        for (int h = 0; h < 2; h++) {
            __half2 p0 = __floats2half2_rn(av[2*h].x, av[2*h].y);
            __half2 p1 = __floats2half2_rn(av[2*h].z, av[2*h].w);
            __half2 p2 = __floats2half2_rn(av[2*h+1].x, av[2*h+1].y);
            __half2 p3 = __floats2half2_rn(av[2*h+1].z, av[2*h+1].w);
            uint4 u;
            u.x = *reinterpret_cast<unsigned*>(&p0);
            u.y = *reinterpret_cast<unsigned*>(&p1);
            u.z = *reinterpret_cast<unsigned*>(&p2);
            u.w = *reinterpret_cast<unsigned*>(&p3);
            *reinterpret_cast<uint4*>(sm + stg * STG_BYTES + swz128(ar, bc + h)) = u;
        }
    };
    auto LOAD_B = [&](int i, int stg) {
        const uint32_t db = sbase0 + stg * STG_BYTES + B_OFF;
        #pragma unroll
        for (int it = 0; it < 5; it++) {
            int idx = t + it * 256;
            if (idx < 1152) {
                int n = idx >> 3, c = idx & 7;
                const __half* g = Pt_f16 + (size_t)n * N_NODES
                                + kbase + i * CH_K + c * 8;
                CP_ASYNC16(db + swz128(n, c), g);
            }
        }
    };
    auto COMPUTE_KS = [&](uint32_t ab, uint32_t bb, int ks) {
        uint32_t a0[4], a1[4];
        {
            const int kc = 2 * ks + (lane >> 4);
            LDSM_X4(a0, ab + swz128(m0 + (lane & 15), kc));
            LDSM_X4(a1, ab + swz128(m0 + 16 + (lane & 15), kc));
        }
        const int kcb = 2 * ks + ((lane >> 3) & 1);
        #pragma unroll
        for (int jg = 0; jg < 4; jg++) {
            int n = n0 + jg * 16 + ((lane >> 4) << 3) + (lane & 7);
            uint32_t b[4];
            LDSM_X4(b, bb + swz128(n, kcb));
            MMA16816(C0[2*jg],   a0, b[0], b[1]);
            MMA16816(C0[2*jg+1], a0, b[2], b[3]);
            MMA16816(C1[2*jg],   a1, b[0], b[1]);
            MMA16816(C1[2*jg+1], a1, b[2], b[3]);
        }
        {
            int n = n0 + 64 + (lane & 7);
            uint32_t b0, b1;
            LDSM_X2(b0, b1, bb + swz128(n, kcb));
            MMA16816(C0[8], a0, b0, b1);
            MMA16816(C1[8], a1, b0, b1);
        }
    };

    // ---- prologue: fill stage 0 ----
    LDG_A(0, 0); STS_A(0, 0);
    LDG_A(0, 1); STS_A(0, 1);
    LOAD_B(0, 0); CP_COMMIT(); CP_WAIT0();
    __syncthreads();

    // ---- main loop: one barrier per 64-K chunk ----
    for (int i = 0; i < NCH; i++) {
        const int s = i & 1;
        const bool more = (i + 1 < NCH);
        const uint32_t ab = sbase0 + s * STG_BYTES;
        const uint32_t bb = ab + B_OFF;

        if (more) { LOAD_B(i + 1, s ^ 1); CP_COMMIT(); LDG_A(i + 1, 0); }
        COMPUTE_KS(ab, bb, 0);
        COMPUTE_KS(ab, bb, 1);
        if (more) { STS_A(s ^ 1, 0); LDG_A(i + 1, 1); }
        COMPUTE_KS(ab, bb, 2);
        COMPUTE_KS(ab, bb, 3);
        if (more) { STS_A(s ^ 1, 1); CP_WAIT0(); }
        __syncthreads();
    }

    // ---- epilogue: fp32 partials ----
    {
        const int rowb = r0 + m0 + (lane >> 2);
        const int col0 = n0 + (lane & 3) * 2;
        float* base = &part_buf[(size_t)split * N_NODES * NCOLS];
        #pragma unroll
        for (int j = 0; j < 9; j++) {
            const int col = col0 + j * 8;
            *reinterpret_cast<float2*>(&base[(size_t)rowb * NCOLS + col]) =
                make_float2(C0[j][0], C0[j][1]);
            *reinterpret_cast<float2*>(&base[(size_t)(rowb + 8) * NCOLS + col]) =
                make_float2(C0[j][2], C0[j][3]);
            *reinterpret_cast<float2*>(&base[(size_t)(rowb + 16) * NCOLS + col]) =
                make_float2(C1[j][0], C1[j][1]);
            *reinterpret_cast<float2*>(&base[(size_t)(rowb + 24) * NCOLS + col]) =
                make_float2(C1[j][2], C1[j][3]);
        }
    }
}

// ---------------------------------------------------------------------------
// Combine: out[row][c] = relu( (Σ_s p_s)[c] / (Σ_s p_s)[128] )
// ---------------------------------------------------------------------------
__global__ __launch_bounds__(256)
void gat_combine(float* __restrict__ out)
{
    const int idx = blockIdx.x * 256 + threadIdx.x;
    const int row = idx >> 7;
    const int c   = idx & 127;
    float num = 0.0f, den = 0.0f;
    #pragma unroll
    for (int s = 0; s < SPLITS; s++) {
        const float* p = &part_buf[((size_t)s * N_NODES + row) * NCOLS];
        num += p[c];
        den += p[128];
    }
    out[idx] = fmaxf(num / den, 0.0f);
}

// ---------------------------------------------------------------------------
extern "C" void kernel_launch(void* const* d_in, const int* in_sizes, int n_in,
                              void* d_out, int out_size)
{
    const float* X   = (const float*)d_in[0];
    const float* A   = (const float*)d_in[1];
    const float* W   = (const float*)d_in[2];
    const float* a_w = (const float*)d_in[3];
    float* out = (float*)d_out;

    cudaFuncSetAttribute(gat_phase2,
                         cudaFuncAttributeMaxDynamicSharedMemorySize, PH2_SMEM);

    gat_phase1<<<N_NODES / 16, 256>>>(X, W, a_w);
    gat_scale<<<(N_NODES / 32) * 4, 256>>>();
    gat_phase2<<<64 * SPLITS, 256, PH2_SMEM>>>(A);
    gat_combine<<<(N_NODES * OUT_DIM) / 256, 256>>>(out);
}